// round 10
// baseline (speedup 1.0000x reference)
#include <cuda_runtime.h>
#include <cuda_fp16.h>
#include <math.h>
#include <stdint.h>

#define N_NODES 500000
#define N_SEG   10000
#define M_PAD   10240            // 40 * 256
#define DIM     256
#define NGATE   1024
#define QSTAR   512
#define NITER   6

// ---------------- scratch (device globals) -----------------------------------
__device__ half  g_featsh[(size_t)N_NODES * DIM];            // fp16 feats copy, 256 MB
__device__ half  g_qstar[(size_t)M_PAD * 512];               // fp16 [q|r]
__device__ half  g_hh[2 * 3 * (size_t)M_PAD * 256];           // fp16 h, ping-pong x 3 layers
__device__ float g_c[3 * (size_t)M_PAD * DIM];
__device__ float g_hq[(size_t)M_PAD * DIM];                   // fp32 q for attn
__device__ half  g_w_ih[3][(size_t)NGATE * 512];              // permuted fp16 (K1<=512)
__device__ half  g_w_hh[3][(size_t)NGATE * 256];
__device__ float g_bp[3 * NGATE];
__device__ int   g_start[N_SEG + 1];

// ---------------- helpers ------------------------------------------------------
__device__ __forceinline__ uint32_t smem_u32(const void* p) {
    return (uint32_t)__cvta_generic_to_shared(p);
}
__device__ __forceinline__ void cp16(uint32_t dst, const void* src) {
    asm volatile("cp.async.cg.shared.global [%0], [%1], 16;" :: "r"(dst), "l"(src));
}
#define CP_COMMIT() asm volatile("cp.async.commit_group;" ::: "memory")
#define CP_WAIT(n)  asm volatile("cp.async.wait_group %0;" :: "n"(n) : "memory")

__device__ __forceinline__ void ldsm_x4(uint32_t& r0, uint32_t& r1, uint32_t& r2, uint32_t& r3,
                                        uint32_t addr) {
    asm volatile("ldmatrix.sync.aligned.m8n8.x4.shared.b16 {%0,%1,%2,%3}, [%4];"
        : "=r"(r0), "=r"(r1), "=r"(r2), "=r"(r3) : "r"(addr));
}
__device__ __forceinline__ void mma_f16(float4& d, const uint32_t* a, uint32_t b0, uint32_t b1) {
    asm volatile(
        "mma.sync.aligned.m16n8k16.row.col.f32.f16.f16.f32 "
        "{%0,%1,%2,%3}, {%4,%5,%6,%7}, {%8,%9}, {%0,%1,%2,%3};"
        : "+f"(d.x), "+f"(d.y), "+f"(d.z), "+f"(d.w)
        : "r"(a[0]), "r"(a[1]), "r"(a[2]), "r"(a[3]), "r"(b0), "r"(b1));
}

__device__ __forceinline__ float sigf(float x) { return 1.0f / (1.0f + __expf(-x)); }
__device__ __forceinline__ float tanhfast(float x) { return 2.0f / (1.0f + __expf(-2.0f * x)) - 1.0f; }

// ---------------- prep: convert + permute weights to gate-interleaved fp16 -----
struct PermArgs {
    const float* w_ih[3]; const float* w_hh[3];
    const float* b_ih[3]; const float* b_hh[3];
    int K1[3];
};
__global__ void prep_kernel(PermArgs pa) {
    int l = blockIdx.y;
    int K1 = pa.K1[l];
    half* wih = g_w_ih[l];
    half* whh = g_w_hh[l];
    int n_ih = NGATE * K1, n_hh = NGATE * DIM;
    int total = n_ih + n_hh + NGATE;
    for (int i = blockIdx.x * blockDim.x + threadIdx.x; i < total; i += gridDim.x * blockDim.x) {
        if (i < n_ih) {
            int r = i / K1, k = i - r * K1;
            int u = r >> 2, g = r & 3;
            wih[i] = __float2half_rn(pa.w_ih[l][(size_t)(g * 256 + u) * K1 + k]);
        } else if (i < n_ih + n_hh) {
            int j = i - n_ih;
            int r = j / DIM, k = j - r * DIM;
            int u = r >> 2, g = r & 3;
            whh[j] = __float2half_rn(pa.w_hh[l][(size_t)(g * 256 + u) * DIM + k]);
        } else {
            int r = i - n_ih - n_hh;
            int u = r >> 2, g = r & 3;
            g_bp[l * NGATE + r] = pa.b_ih[l][g * 256 + u] + pa.b_hh[l][g * 256 + u];
        }
    }
}

// ---------------- feats -> fp16 one-time conversion -----------------------------
__global__ void feats_conv_kernel(const float* __restrict__ feats) {
    size_t i = ((size_t)blockIdx.x * blockDim.x + threadIdx.x) * 4;
    size_t stride = (size_t)gridDim.x * blockDim.x * 4;
    const size_t n = (size_t)N_NODES * DIM;
    for (; i < n; i += stride) {
        float4 v = *(const float4*)(feats + i);
        half2 h0 = __floats2half2_rn(v.x, v.y);
        half2 h1 = __floats2half2_rn(v.z, v.w);
        *(uint2*)(g_featsh + i) = make_uint2(
            *(uint32_t*)&h0, *(uint32_t*)&h1);
    }
}

// ---------------- init ----------------------------------------------------------
__global__ void init_kernel(const int* __restrict__ seg) {
    size_t gid = (size_t)blockIdx.x * blockDim.x + threadIdx.x;
    size_t stride = (size_t)gridDim.x * blockDim.x;
    const size_t nq = (size_t)M_PAD * 512;
    const size_t nh = (size_t)2 * 3 * M_PAD * 256;
    const size_t nc = (size_t)3 * M_PAD * DIM;
    half z = __float2half_rn(0.0f);
    for (size_t i = gid; i < nq; i += stride) g_qstar[i] = z;
    for (size_t i = gid; i < nh; i += stride) g_hh[i] = z;
    for (size_t i = gid; i < nc; i += stride) g_c[i] = 0.0f;
    if (gid <= N_SEG) {
        int s = (int)gid;
        int lo = 0, hi = N_NODES;
        while (lo < hi) { int mid = (lo + hi) >> 1; if (seg[mid] < s) lo = mid + 1; else hi = mid; }
        g_start[s] = lo;
    }
}

// ---------------- fp16 HMMA GEMM + fused LSTM cell ------------------------------
// 256x128 CTA tile, 512 threads (16 warps: 8 along M x 2 along N).
// 3-stage cp.async pipeline (48 KB/stage: A 32KB + B 16KB), one barrier/chunk.
#define A_BYTES  32768
#define STAGE_SZ 49152
#define SMEM_GE  (3 * STAGE_SZ)

template<int K1>
__global__ __launch_bounds__(512, 1)
void gemm_lstm_mma(const half* __restrict__ A1, const half* __restrict__ W1,
                   const half* __restrict__ A2, const half* __restrict__ W2,
                   const float* __restrict__ bias,
                   float* __restrict__ c, half* __restrict__ hout,
                   float* __restrict__ hq, int write_q) {
    extern __shared__ __align__(128) char smem[];
    const uint32_t sbase = smem_u32(smem);
    const int tid = threadIdx.x;
    const int lane = tid & 31;
    const int wid = tid >> 5;
    const int warp_m = wid & 7;       // 8 warps along M (32 rows each) = 256
    const int warp_n = wid >> 3;      // 2 warps along N (64 cols each)
    const int bm = blockIdx.x * 256;
    const int bn = blockIdx.y * 128;

    constexpr int C1 = K1 / 64;       // ih chunks (8 or 4)
    constexpr int NC = C1 + 4;        // + hh chunks (K2=256)

    // loader: A rows r0+64q (q<4), B rows r0+64q (q<2); sg = tid&7 fixed.
    const int r0 = tid >> 3;          // 0..63
    const int sg = tid & 7;
    const uint32_t so0 = (uint32_t)(r0 * 128 + ((sg * 16) ^ ((r0 & 7) << 4)));
    const half* a1p = A1 + (size_t)(bm + r0) * K1 + sg * 8;
    const half* w1p = W1 + (size_t)(bn + r0) * K1 + sg * 8;
    const half* a2p = A2 + (size_t)(bm + r0) * 256 + sg * 8;
    const half* w2p = W2 + (size_t)(bn + r0) * 256 + sg * 8;

    auto load_chunk = [&](int g, int st) {
        const uint32_t sA = sbase + st * STAGE_SZ + so0;
        const uint32_t sB = sA + A_BYTES;
        if (g < C1) {
            const int off = g * 64;
            constexpr size_t ST = (size_t)64 * K1;
#pragma unroll
            for (int q = 0; q < 4; q++) cp16(sA + q * 8192, a1p + q * ST + off);
#pragma unroll
            for (int q = 0; q < 2; q++) cp16(sB + q * 8192, w1p + q * ST + off);
        } else {
            const int off = (g - C1) * 64;
            constexpr size_t ST = (size_t)64 * 256;
#pragma unroll
            for (int q = 0; q < 4; q++) cp16(sA + q * 8192, a2p + q * ST + off);
#pragma unroll
            for (int q = 0; q < 2; q++) cp16(sB + q * 8192, w2p + q * ST + off);
        }
        CP_COMMIT();
    };

    float4 acc[2][8];
#pragma unroll
    for (int i = 0; i < 2; i++)
#pragma unroll
        for (int j = 0; j < 8; j++) acc[i][j] = make_float4(0.f, 0.f, 0.f, 0.f);

    load_chunk(0, 0);
    load_chunk(1, 1);

    // hoisted ldmatrix addressing: addr = stagebase + base + ((ks*32) ^ xc)
    const int koff = (lane >> 4) * 16;
    uint32_t a_base[2], a_xc[2], b_base[4], b_xc[4];
#pragma unroll
    for (int tm = 0; tm < 2; tm++) {
        int row = warp_m * 32 + tm * 16 + (lane & 15);
        a_base[tm] = sbase + row * 128;
        a_xc[tm] = (uint32_t)(koff ^ ((row & 7) << 4));
    }
#pragma unroll
    for (int tn2 = 0; tn2 < 4; tn2++) {
        int row = warp_n * 64 + tn2 * 16 + (lane & 15);
        b_base[tn2] = sbase + A_BYTES + row * 128;
        b_xc[tn2] = (uint32_t)(koff ^ ((row & 7) << 4));
    }

    int st_cur = 0, st_nxt = 2;

#pragma unroll 1
    for (int g = 0; g < NC; g++) {
        if (g + 1 < NC) { CP_WAIT(1); } else { CP_WAIT(0); }
        __syncthreads();

        if (g + 2 < NC) load_chunk(g + 2, st_nxt);

        const uint32_t stoff = st_cur * STAGE_SZ;
#pragma unroll
        for (int ks = 0; ks < 4; ks++) {
            uint32_t a[2][4];
#pragma unroll
            for (int tm = 0; tm < 2; tm++)
                ldsm_x4(a[tm][0], a[tm][1], a[tm][2], a[tm][3],
                        a_base[tm] + stoff + ((uint32_t)(ks * 32) ^ a_xc[tm]));
            uint32_t b[4][4];
#pragma unroll
            for (int tn2 = 0; tn2 < 4; tn2++)
                ldsm_x4(b[tn2][0], b[tn2][1], b[tn2][2], b[tn2][3],
                        b_base[tn2] + stoff + ((uint32_t)(ks * 32) ^ b_xc[tn2]));
#pragma unroll
            for (int tm = 0; tm < 2; tm++)
#pragma unroll
                for (int tn2 = 0; tn2 < 4; tn2++) {
                    mma_f16(acc[tm][tn2 * 2 + 0], a[tm], b[tn2][0], b[tn2][2]);
                    mma_f16(acc[tm][tn2 * 2 + 1], a[tm], b[tn2][1], b[tn2][3]);
                }
        }

        st_cur = (st_cur == 2) ? 0 : st_cur + 1;
        st_nxt = (st_nxt == 2) ? 0 : st_nxt + 1;
    }

    // ---- fused LSTM epilogue ----
    const bool even = !(lane & 1);
#pragma unroll
    for (int tm = 0; tm < 2; tm++) {
#pragma unroll
        for (int tn = 0; tn < 8; tn++) {
            float4 d = acc[tm][tn];
            float e0 = __shfl_xor_sync(0xffffffffu, d.x, 1);
            float e1 = __shfl_xor_sync(0xffffffffu, d.y, 1);
            float e2 = __shfl_xor_sync(0xffffffffu, d.z, 1);
            float e3 = __shfl_xor_sync(0xffffffffu, d.w, 1);
            if (even) {
                int col = bn + warp_n * 64 + tn * 8 + (lane & 3) * 2;
                int u = col >> 2;
                float4 bi = *(const float4*)&bias[col];
                int rA = bm + warp_m * 32 + tm * 16 + (lane >> 2);
#pragma unroll
                for (int rh = 0; rh < 2; rh++) {
                    int row = rA + rh * 8;
                    float gi = (rh ? d.z : d.x) + bi.x;
                    float gf = (rh ? d.w : d.y) + bi.y;
                    float gg = (rh ? e2 : e0) + bi.z;
                    float go = (rh ? e3 : e1) + bi.w;
                    size_t cidx = (size_t)row * DIM + u;
                    float cn = sigf(gf) * c[cidx] + sigf(gi) * tanhfast(gg);
                    c[cidx] = cn;
                    float hn = sigf(go) * tanhfast(cn);
                    hout[(size_t)row * 256 + u] = __float2half_rn(hn);
                    if (write_q) hq[(size_t)row * DIM + u] = hn;
                }
            }
        }
    }
}

// ---------------- fused attention: online softmax per segment (fp16 feats) ------
__global__ void attn_kernel(const float* __restrict__ q, float* __restrict__ out) {
    const int s = blockIdx.x;
    const int lo = g_start[s], hi = g_start[s + 1];
    const int w = threadIdx.x >> 5;
    const int lane = threadIdx.x & 31;

    __shared__ float sm_m[8];
    __shared__ float sm_s[8];
    __shared__ float sm_r[8][256];

    // q: 8 floats per lane (dims lane*8 .. lane*8+7)
    float qf[8];
    *(float4*)&qf[0] = *(const float4*)(q + (size_t)s * DIM + lane * 8);
    *(float4*)&qf[4] = *(const float4*)(q + (size_t)s * DIM + lane * 8 + 4);

    float m = -INFINITY, ssum = 0.0f;
    float r[8];
#pragma unroll
    for (int j = 0; j < 8; j++) r[j] = 0.0f;

    for (int n = lo + w; n < hi; n += 8) {
        uint4 fv = *(const uint4*)(g_featsh + (size_t)n * DIM + lane * 8);
        float2 f0 = __half22float2(*(half2*)&fv.x);
        float2 f1 = __half22float2(*(half2*)&fv.y);
        float2 f2 = __half22float2(*(half2*)&fv.z);
        float2 f3 = __half22float2(*(half2*)&fv.w);
        float ff[8] = {f0.x, f0.y, f1.x, f1.y, f2.x, f2.y, f3.x, f3.y};
        float d = 0.0f;
#pragma unroll
        for (int j = 0; j < 8; j++) d = fmaf(ff[j], qf[j], d);
#pragma unroll
        for (int o = 16; o > 0; o >>= 1) d += __shfl_xor_sync(0xffffffffu, d, o);

        float mn = fmaxf(m, d);
        float sc = __expf(m - mn);
        float p  = __expf(d - mn);
        ssum = ssum * sc + p;
#pragma unroll
        for (int j = 0; j < 8; j++) r[j] = r[j] * sc + p * ff[j];
        m = mn;
    }

    if (lane == 0) { sm_m[w] = m; sm_s[w] = ssum; }
    *(float4*)&sm_r[w][lane * 8]     = *(float4*)&r[0];
    *(float4*)&sm_r[w][lane * 8 + 4] = *(float4*)&r[4];
    __syncthreads();

    const int t = threadIdx.x;
    float M = -INFINITY;
#pragma unroll
    for (int k = 0; k < 8; k++)
        if (sm_s[k] > 0.0f) M = fmaxf(M, sm_m[k]);
    float S = 0.0f, R = 0.0f;
#pragma unroll
    for (int k = 0; k < 8; k++) {
        if (sm_s[k] > 0.0f) {
            float sc = __expf(sm_m[k] - M);
            S += sm_s[k] * sc;
            R += sm_r[k][t] * sc;
        }
    }
    float rv = (S > 0.0f) ? R / S : 0.0f;
    float qv_ = q[(size_t)s * DIM + t];
    out[(size_t)s * QSTAR + t]       = qv_;
    out[(size_t)s * QSTAR + DIM + t] = rv;

    half* qs = g_qstar + (size_t)s * 512;
    qs[t]       = __float2half_rn(qv_);
    qs[256 + t] = __float2half_rn(rv);
}

// ---------------- host orchestration -------------------------------------------
extern "C" void kernel_launch(void* const* d_in, const int* in_sizes, int n_in,
                              void* d_out, int out_size) {
    const float* feats = (const float*)d_in[0];
    const int* seg = (const int*)d_in[1];
    float* out = (float*)d_out;

    PermArgs pa;
    for (int l = 0; l < 3; l++) {
        pa.w_ih[l] = (const float*)d_in[2 + 4 * l];
        pa.w_hh[l] = (const float*)d_in[3 + 4 * l];
        pa.b_ih[l] = (const float*)d_in[4 + 4 * l];
        pa.b_hh[l] = (const float*)d_in[5 + 4 * l];
        pa.K1[l] = (l == 0) ? QSTAR : DIM;
    }

    half *qs, *hh; float *c, *hq, *bp; half *wih[3], *whh[3];
    cudaGetSymbolAddress((void**)&qs, g_qstar);
    cudaGetSymbolAddress((void**)&hh, g_hh);
    cudaGetSymbolAddress((void**)&c, g_c);
    cudaGetSymbolAddress((void**)&hq, g_hq);
    cudaGetSymbolAddress((void**)&bp, g_bp);
    {
        half* base_ih; half* base_hh;
        cudaGetSymbolAddress((void**)&base_ih, g_w_ih);
        cudaGetSymbolAddress((void**)&base_hh, g_w_hh);
        for (int l = 0; l < 3; l++) {
            wih[l] = base_ih + (size_t)l * NGATE * 512;
            whh[l] = base_hh + (size_t)l * NGATE * 256;
        }
    }

    cudaFuncSetAttribute(gemm_lstm_mma<512>, cudaFuncAttributeMaxDynamicSharedMemorySize, SMEM_GE);
    cudaFuncSetAttribute(gemm_lstm_mma<256>, cudaFuncAttributeMaxDynamicSharedMemorySize, SMEM_GE);

    dim3 pgrid(256, 3);
    prep_kernel<<<pgrid, 256>>>(pa);
    feats_conv_kernel<<<2048, 256>>>(feats);
    init_kernel<<<1184, 256>>>(seg);

    const size_t SDH = (size_t)M_PAD * 256;   // h layer stride
    dim3 ggrid(M_PAD / 256, NGATE / 128);

    for (int it = 0; it < NITER; it++) {
        half* hin  = hh + (size_t)(it & 1) * 3 * SDH;
        half* hout = hh + (size_t)((it + 1) & 1) * 3 * SDH;
        for (int l = 0; l < 3; l++) {
            const half* A1 = (l == 0) ? qs : (hout + (size_t)(l - 1) * SDH);
            if (l == 0) {
                gemm_lstm_mma<512><<<ggrid, 512, SMEM_GE>>>(
                    A1, wih[l], hin + (size_t)l * SDH, whh[l],
                    bp + l * NGATE, c + (size_t)l * M_PAD * DIM,
                    hout + (size_t)l * SDH, hq, 0);
            } else {
                gemm_lstm_mma<256><<<ggrid, 512, SMEM_GE>>>(
                    A1, wih[l], hin + (size_t)l * SDH, whh[l],
                    bp + l * NGATE, c + (size_t)l * M_PAD * DIM,
                    hout + (size_t)l * SDH, hq, (l == 2) ? 1 : 0);
            }
        }
        attn_kernel<<<N_SEG, 256>>>(hq, out);
    }
}

// round 11
// speedup vs baseline: 1.1208x; 1.1208x over previous
#include <cuda_runtime.h>
#include <cuda_fp16.h>
#include <math.h>
#include <stdint.h>

#define N_NODES 500000
#define N_SEG   10000
#define M_PAD   10112            // 79 * 128
#define DIM     256
#define NGATE   1024
#define QSTAR   512
#define NITER   6

// ---------------- scratch (device globals) -----------------------------------
__device__ half  g_featsh[(size_t)N_NODES * DIM];            // fp16 feats copy, 256 MB
__device__ half  g_qstar[(size_t)M_PAD * 512];               // fp16 [q|r]
__device__ half  g_hh[2 * 3 * (size_t)M_PAD * 256];           // fp16 h, ping-pong x 3 layers
__device__ float g_c[3 * (size_t)M_PAD * DIM];
__device__ float g_hq[(size_t)M_PAD * DIM];                   // fp32 q for attn
__device__ half  g_w_ih[3][(size_t)NGATE * 512];              // permuted fp16 (K1<=512)
__device__ half  g_w_hh[3][(size_t)NGATE * 256];
__device__ float g_bp[3 * NGATE];
__device__ int   g_start[N_SEG + 1];

// ---------------- helpers ------------------------------------------------------
__device__ __forceinline__ uint32_t smem_u32(const void* p) {
    return (uint32_t)__cvta_generic_to_shared(p);
}
__device__ __forceinline__ void cp16(uint32_t dst, const void* src) {
    asm volatile("cp.async.cg.shared.global [%0], [%1], 16;" :: "r"(dst), "l"(src));
}
#define CP_COMMIT() asm volatile("cp.async.commit_group;" ::: "memory")
#define CP_WAIT(n)  asm volatile("cp.async.wait_group %0;" :: "n"(n) : "memory")

__device__ __forceinline__ void ldsm_x4(uint32_t& r0, uint32_t& r1, uint32_t& r2, uint32_t& r3,
                                        uint32_t addr) {
    asm volatile("ldmatrix.sync.aligned.m8n8.x4.shared.b16 {%0,%1,%2,%3}, [%4];"
        : "=r"(r0), "=r"(r1), "=r"(r2), "=r"(r3) : "r"(addr));
}
__device__ __forceinline__ void mma_f16(float4& d, const uint32_t* a, uint32_t b0, uint32_t b1) {
    asm volatile(
        "mma.sync.aligned.m16n8k16.row.col.f32.f16.f16.f32 "
        "{%0,%1,%2,%3}, {%4,%5,%6,%7}, {%8,%9}, {%0,%1,%2,%3};"
        : "+f"(d.x), "+f"(d.y), "+f"(d.z), "+f"(d.w)
        : "r"(a[0]), "r"(a[1]), "r"(a[2]), "r"(a[3]), "r"(b0), "r"(b1));
}

__device__ __forceinline__ float sigf(float x) { return 1.0f / (1.0f + __expf(-x)); }
__device__ __forceinline__ float tanhfast(float x) { return 2.0f / (1.0f + __expf(-2.0f * x)) - 1.0f; }

// ---------------- prep: convert + permute weights to gate-interleaved fp16 -----
struct PermArgs {
    const float* w_ih[3]; const float* w_hh[3];
    const float* b_ih[3]; const float* b_hh[3];
    int K1[3];
};
__global__ void prep_kernel(PermArgs pa) {
    int l = blockIdx.y;
    int K1 = pa.K1[l];
    half* wih = g_w_ih[l];
    half* whh = g_w_hh[l];
    int n_ih = NGATE * K1, n_hh = NGATE * DIM;
    int total = n_ih + n_hh + NGATE;
    for (int i = blockIdx.x * blockDim.x + threadIdx.x; i < total; i += gridDim.x * blockDim.x) {
        if (i < n_ih) {
            int r = i / K1, k = i - r * K1;
            int u = r >> 2, g = r & 3;
            wih[i] = __float2half_rn(pa.w_ih[l][(size_t)(g * 256 + u) * K1 + k]);
        } else if (i < n_ih + n_hh) {
            int j = i - n_ih;
            int r = j / DIM, k = j - r * DIM;
            int u = r >> 2, g = r & 3;
            whh[j] = __float2half_rn(pa.w_hh[l][(size_t)(g * 256 + u) * DIM + k]);
        } else {
            int r = i - n_ih - n_hh;
            int u = r >> 2, g = r & 3;
            g_bp[l * NGATE + r] = pa.b_ih[l][g * 256 + u] + pa.b_hh[l][g * 256 + u];
        }
    }
}

// ---------------- feats -> fp16 one-time conversion -----------------------------
__global__ void feats_conv_kernel(const float* __restrict__ feats) {
    size_t i = ((size_t)blockIdx.x * blockDim.x + threadIdx.x) * 4;
    size_t stride = (size_t)gridDim.x * blockDim.x * 4;
    const size_t n = (size_t)N_NODES * DIM;
    for (; i < n; i += stride) {
        float4 v = *(const float4*)(feats + i);
        half2 h0 = __floats2half2_rn(v.x, v.y);
        half2 h1 = __floats2half2_rn(v.z, v.w);
        *(uint2*)(g_featsh + i) = make_uint2(*(uint32_t*)&h0, *(uint32_t*)&h1);
    }
}

// ---------------- init ----------------------------------------------------------
__global__ void init_kernel(const int* __restrict__ seg) {
    size_t gid = (size_t)blockIdx.x * blockDim.x + threadIdx.x;
    size_t stride = (size_t)gridDim.x * blockDim.x;
    const size_t nq = (size_t)M_PAD * 512;
    const size_t nh = (size_t)2 * 3 * M_PAD * 256;
    const size_t nc = (size_t)3 * M_PAD * DIM;
    half z = __float2half_rn(0.0f);
    for (size_t i = gid; i < nq; i += stride) g_qstar[i] = z;
    for (size_t i = gid; i < nh; i += stride) g_hh[i] = z;
    for (size_t i = gid; i < nc; i += stride) g_c[i] = 0.0f;
    if (gid <= N_SEG) {
        int s = (int)gid;
        int lo = 0, hi = N_NODES;
        while (lo < hi) { int mid = (lo + hi) >> 1; if (seg[mid] < s) lo = mid + 1; else hi = mid; }
        g_start[s] = lo;
    }
}

// ---------------- fp16 HMMA GEMM + fused LSTM cell (R9 config) ------------------
// 128x128 CTA tile, 256 threads (8 warps: 4 M x 2 N), 3-stage cp.async pipeline.
#define SM_BUF   16384
#define STAGE_SZ 32768
#define SMEM_GE  (3 * STAGE_SZ)

template<int K1>
__global__ __launch_bounds__(256, 2)
void gemm_lstm_mma(const half* __restrict__ A1, const half* __restrict__ W1,
                   const half* __restrict__ A2, const half* __restrict__ W2,
                   const float* __restrict__ bias,
                   float* __restrict__ c, half* __restrict__ hout,
                   float* __restrict__ hq, int write_q) {
    extern __shared__ __align__(128) char smem[];
    const uint32_t sbase = smem_u32(smem);
    const int tid = threadIdx.x;
    const int lane = tid & 31;
    const int wid = tid >> 5;
    const int warp_m = wid & 3;
    const int warp_n = wid >> 2;
    const int bm = blockIdx.x * 128;
    const int bn = blockIdx.y * 128;

    constexpr int C1 = K1 / 64;          // ih chunks (8 or 4)
    constexpr int NC = C1 + 4;           // + hh chunks (K2=256)

    const int r0 = tid >> 3;
    const int sg = tid & 7;
    const uint32_t so0 = (uint32_t)(r0 * 128 + ((sg * 16) ^ ((r0 & 7) << 4)));
    const half* a1p = A1 + (size_t)(bm + r0) * K1 + sg * 8;
    const half* w1p = W1 + (size_t)(bn + r0) * K1 + sg * 8;
    const half* a2p = A2 + (size_t)(bm + r0) * 256 + sg * 8;
    const half* w2p = W2 + (size_t)(bn + r0) * 256 + sg * 8;

    auto load_chunk = [&](int g, int st) {
        const uint32_t sA = sbase + st * STAGE_SZ + so0;
        const uint32_t sB = sA + SM_BUF;
        if (g < C1) {
            const int off = g * 64;
#pragma unroll
            for (int q = 0; q < 4; q++) {
                constexpr size_t ST = (size_t)32 * K1;
                cp16(sA + q * 4096, a1p + q * ST + off);
                cp16(sB + q * 4096, w1p + q * ST + off);
            }
        } else {
            const int off = (g - C1) * 64;
#pragma unroll
            for (int q = 0; q < 4; q++) {
                constexpr size_t ST = (size_t)32 * 256;
                cp16(sA + q * 4096, a2p + q * ST + off);
                cp16(sB + q * 4096, w2p + q * ST + off);
            }
        }
        CP_COMMIT();
    };

    float4 acc[2][8];
#pragma unroll
    for (int i = 0; i < 2; i++)
#pragma unroll
        for (int j = 0; j < 8; j++) acc[i][j] = make_float4(0.f, 0.f, 0.f, 0.f);

    load_chunk(0, 0);
    load_chunk(1, 1);

    const int koff = (lane >> 4) * 16;
    uint32_t a_base[2], a_xc[2], b_base[4], b_xc[4];
#pragma unroll
    for (int tm = 0; tm < 2; tm++) {
        int row = warp_m * 32 + tm * 16 + (lane & 15);
        a_base[tm] = sbase + row * 128;
        a_xc[tm] = (uint32_t)(koff ^ ((row & 7) << 4));
    }
#pragma unroll
    for (int tn2 = 0; tn2 < 4; tn2++) {
        int row = warp_n * 64 + tn2 * 16 + (lane & 15);
        b_base[tn2] = sbase + SM_BUF + row * 128;
        b_xc[tn2] = (uint32_t)(koff ^ ((row & 7) << 4));
    }

    int st_cur = 0, st_nxt = 2;

#pragma unroll 1
    for (int g = 0; g < NC; g++) {
        if (g + 1 < NC) { CP_WAIT(1); } else { CP_WAIT(0); }
        __syncthreads();

        if (g + 2 < NC) load_chunk(g + 2, st_nxt);

        const uint32_t stoff = st_cur * STAGE_SZ;
#pragma unroll
        for (int ks = 0; ks < 4; ks++) {
            uint32_t a[2][4];
#pragma unroll
            for (int tm = 0; tm < 2; tm++)
                ldsm_x4(a[tm][0], a[tm][1], a[tm][2], a[tm][3],
                        a_base[tm] + stoff + ((uint32_t)(ks * 32) ^ a_xc[tm]));
            uint32_t b[4][4];
#pragma unroll
            for (int tn2 = 0; tn2 < 4; tn2++)
                ldsm_x4(b[tn2][0], b[tn2][1], b[tn2][2], b[tn2][3],
                        b_base[tn2] + stoff + ((uint32_t)(ks * 32) ^ b_xc[tn2]));
#pragma unroll
            for (int tm = 0; tm < 2; tm++)
#pragma unroll
                for (int tn2 = 0; tn2 < 4; tn2++) {
                    mma_f16(acc[tm][tn2 * 2 + 0], a[tm], b[tn2][0], b[tn2][2]);
                    mma_f16(acc[tm][tn2 * 2 + 1], a[tm], b[tn2][1], b[tn2][3]);
                }
        }

        st_cur = (st_cur == 2) ? 0 : st_cur + 1;
        st_nxt = (st_nxt == 2) ? 0 : st_nxt + 1;
    }

    // ---- fused LSTM epilogue ----
    const bool even = !(lane & 1);
#pragma unroll
    for (int tm = 0; tm < 2; tm++) {
#pragma unroll
        for (int tn = 0; tn < 8; tn++) {
            float4 d = acc[tm][tn];
            float e0 = __shfl_xor_sync(0xffffffffu, d.x, 1);
            float e1 = __shfl_xor_sync(0xffffffffu, d.y, 1);
            float e2 = __shfl_xor_sync(0xffffffffu, d.z, 1);
            float e3 = __shfl_xor_sync(0xffffffffu, d.w, 1);
            if (even) {
                int col = bn + warp_n * 64 + tn * 8 + (lane & 3) * 2;
                int u = col >> 2;
                float4 bi = *(const float4*)&bias[col];
                int rA = bm + warp_m * 32 + tm * 16 + (lane >> 2);
#pragma unroll
                for (int rh = 0; rh < 2; rh++) {
                    int row = rA + rh * 8;
                    float gi = (rh ? d.z : d.x) + bi.x;
                    float gf = (rh ? d.w : d.y) + bi.y;
                    float gg = (rh ? e2 : e0) + bi.z;
                    float go = (rh ? e3 : e1) + bi.w;
                    size_t cidx = (size_t)row * DIM + u;
                    float cn = sigf(gf) * c[cidx] + sigf(gi) * tanhfast(gg);
                    c[cidx] = cn;
                    float hn = sigf(go) * tanhfast(cn);
                    hout[(size_t)row * 256 + u] = __float2half_rn(hn);
                    if (write_q) hq[(size_t)row * DIM + u] = hn;
                }
            }
        }
    }
}

// ---------------- fused attention: online softmax per segment (fp16 feats) ------
__global__ void attn_kernel(const float* __restrict__ q, float* __restrict__ out) {
    const int s = blockIdx.x;
    const int lo = g_start[s], hi = g_start[s + 1];
    const int w = threadIdx.x >> 5;
    const int lane = threadIdx.x & 31;

    __shared__ float sm_m[8];
    __shared__ float sm_s[8];
    __shared__ float sm_r[8][256];

    float qf[8];
    *(float4*)&qf[0] = *(const float4*)(q + (size_t)s * DIM + lane * 8);
    *(float4*)&qf[4] = *(const float4*)(q + (size_t)s * DIM + lane * 8 + 4);

    float m = -INFINITY, ssum = 0.0f;
    float r[8];
#pragma unroll
    for (int j = 0; j < 8; j++) r[j] = 0.0f;

    for (int n = lo + w; n < hi; n += 8) {
        uint4 fv = *(const uint4*)(g_featsh + (size_t)n * DIM + lane * 8);
        float2 f0 = __half22float2(*(half2*)&fv.x);
        float2 f1 = __half22float2(*(half2*)&fv.y);
        float2 f2 = __half22float2(*(half2*)&fv.z);
        float2 f3 = __half22float2(*(half2*)&fv.w);
        float ff[8] = {f0.x, f0.y, f1.x, f1.y, f2.x, f2.y, f3.x, f3.y};
        float d = 0.0f;
#pragma unroll
        for (int j = 0; j < 8; j++) d = fmaf(ff[j], qf[j], d);
#pragma unroll
        for (int o = 16; o > 0; o >>= 1) d += __shfl_xor_sync(0xffffffffu, d, o);

        float mn = fmaxf(m, d);
        float sc = __expf(m - mn);
        float p  = __expf(d - mn);
        ssum = ssum * sc + p;
#pragma unroll
        for (int j = 0; j < 8; j++) r[j] = r[j] * sc + p * ff[j];
        m = mn;
    }

    if (lane == 0) { sm_m[w] = m; sm_s[w] = ssum; }
    *(float4*)&sm_r[w][lane * 8]     = *(float4*)&r[0];
    *(float4*)&sm_r[w][lane * 8 + 4] = *(float4*)&r[4];
    __syncthreads();

    const int t = threadIdx.x;
    float M = -INFINITY;
#pragma unroll
    for (int k = 0; k < 8; k++)
        if (sm_s[k] > 0.0f) M = fmaxf(M, sm_m[k]);
    float S = 0.0f, R = 0.0f;
#pragma unroll
    for (int k = 0; k < 8; k++) {
        if (sm_s[k] > 0.0f) {
            float sc = __expf(sm_m[k] - M);
            S += sm_s[k] * sc;
            R += sm_r[k][t] * sc;
        }
    }
    float rv = (S > 0.0f) ? R / S : 0.0f;
    float qv_ = q[(size_t)s * DIM + t];
    out[(size_t)s * QSTAR + t]       = qv_;
    out[(size_t)s * QSTAR + DIM + t] = rv;

    half* qs = g_qstar + (size_t)s * 512;
    qs[t]       = __float2half_rn(qv_);
    qs[256 + t] = __float2half_rn(rv);
}

// ---------------- host orchestration -------------------------------------------
extern "C" void kernel_launch(void* const* d_in, const int* in_sizes, int n_in,
                              void* d_out, int out_size) {
    const float* feats = (const float*)d_in[0];
    const int* seg = (const int*)d_in[1];
    float* out = (float*)d_out;

    PermArgs pa;
    for (int l = 0; l < 3; l++) {
        pa.w_ih[l] = (const float*)d_in[2 + 4 * l];
        pa.w_hh[l] = (const float*)d_in[3 + 4 * l];
        pa.b_ih[l] = (const float*)d_in[4 + 4 * l];
        pa.b_hh[l] = (const float*)d_in[5 + 4 * l];
        pa.K1[l] = (l == 0) ? QSTAR : DIM;
    }

    half *qs, *hh; float *c, *hq, *bp; half *wih[3], *whh[3];
    cudaGetSymbolAddress((void**)&qs, g_qstar);
    cudaGetSymbolAddress((void**)&hh, g_hh);
    cudaGetSymbolAddress((void**)&c, g_c);
    cudaGetSymbolAddress((void**)&hq, g_hq);
    cudaGetSymbolAddress((void**)&bp, g_bp);
    {
        half* base_ih; half* base_hh;
        cudaGetSymbolAddress((void**)&base_ih, g_w_ih);
        cudaGetSymbolAddress((void**)&base_hh, g_w_hh);
        for (int l = 0; l < 3; l++) {
            wih[l] = base_ih + (size_t)l * NGATE * 512;
            whh[l] = base_hh + (size_t)l * NGATE * 256;
        }
    }

    cudaFuncSetAttribute(gemm_lstm_mma<512>, cudaFuncAttributeMaxDynamicSharedMemorySize, SMEM_GE);
    cudaFuncSetAttribute(gemm_lstm_mma<256>, cudaFuncAttributeMaxDynamicSharedMemorySize, SMEM_GE);

    dim3 pgrid(256, 3);
    prep_kernel<<<pgrid, 256>>>(pa);
    feats_conv_kernel<<<2048, 256>>>(feats);
    init_kernel<<<1184, 256>>>(seg);

    const size_t SDH = (size_t)M_PAD * 256;   // h layer stride
    dim3 ggrid(M_PAD / 128, NGATE / 128);

    for (int it = 0; it < NITER; it++) {
        half* hin  = hh + (size_t)(it & 1) * 3 * SDH;
        half* hout = hh + (size_t)((it + 1) & 1) * 3 * SDH;
        for (int l = 0; l < 3; l++) {
            const half* A1 = (l == 0) ? qs : (hout + (size_t)(l - 1) * SDH);
            if (l == 0) {
                gemm_lstm_mma<512><<<ggrid, 256, SMEM_GE>>>(
                    A1, wih[l], hin + (size_t)l * SDH, whh[l],
                    bp + l * NGATE, c + (size_t)l * M_PAD * DIM,
                    hout + (size_t)l * SDH, hq, 0);
            } else {
                gemm_lstm_mma<256><<<ggrid, 256, SMEM_GE>>>(
                    A1, wih[l], hin + (size_t)l * SDH, whh[l],
                    bp + l * NGATE, c + (size_t)l * M_PAD * DIM,
                    hout + (size_t)l * SDH, hq, (l == 2) ? 1 : 0);
            }
        }
        attn_kernel<<<N_SEG, 256>>>(hq, out);
    }
}

// round 12
// speedup vs baseline: 1.1628x; 1.0375x over previous
#include <cuda_runtime.h>
#include <cuda_fp16.h>
#include <math.h>
#include <stdint.h>

#define N_NODES 500000
#define N_SEG   10000
#define M_PAD   10112            // 79 * 128
#define DIM     256
#define NGATE   1024
#define QSTAR   512
#define NITER   6
#define NCTA    632              // 79 * 8 tiles per GEMM unit
#define PARTSZ  ((size_t)NCTA * 256 * 16)   // float4s per partial layer

// ---------------- scratch (device globals) -----------------------------------
__device__ half   g_featsh[(size_t)N_NODES * DIM];           // fp16 feats copy
__device__ half   g_qstar[(size_t)M_PAD * 512];              // fp16 [q|r]
__device__ half   g_hh[2 * 3 * (size_t)M_PAD * 256];          // fp16 h ping-pong x 3
__device__ float  g_c[3 * (size_t)M_PAD * DIM];
__device__ float  g_hq[(size_t)M_PAD * DIM];                  // fp32 q for attn
__device__ half   g_w_ih[3][(size_t)NGATE * 512];
__device__ half   g_w_hh[3][(size_t)NGATE * 256];
__device__ float  g_bp[3 * NGATE];
__device__ float4 g_part[2 * PARTSZ];                         // hh partial gates, 83 MB
__device__ int    g_start[N_SEG + 1];

// ---------------- helpers ------------------------------------------------------
__device__ __forceinline__ uint32_t smem_u32(const void* p) {
    return (uint32_t)__cvta_generic_to_shared(p);
}
__device__ __forceinline__ void cp16(uint32_t dst, const void* src) {
    asm volatile("cp.async.cg.shared.global [%0], [%1], 16;" :: "r"(dst), "l"(src));
}
#define CP_COMMIT() asm volatile("cp.async.commit_group;" ::: "memory")
#define CP_WAIT(n)  asm volatile("cp.async.wait_group %0;" :: "n"(n) : "memory")

__device__ __forceinline__ void ldsm_x4(uint32_t& r0, uint32_t& r1, uint32_t& r2, uint32_t& r3,
                                        uint32_t addr) {
    asm volatile("ldmatrix.sync.aligned.m8n8.x4.shared.b16 {%0,%1,%2,%3}, [%4];"
        : "=r"(r0), "=r"(r1), "=r"(r2), "=r"(r3) : "r"(addr));
}
__device__ __forceinline__ void mma_f16(float4& d, const uint32_t* a, uint32_t b0, uint32_t b1) {
    asm volatile(
        "mma.sync.aligned.m16n8k16.row.col.f32.f16.f16.f32 "
        "{%0,%1,%2,%3}, {%4,%5,%6,%7}, {%8,%9}, {%0,%1,%2,%3};"
        : "+f"(d.x), "+f"(d.y), "+f"(d.z), "+f"(d.w)
        : "r"(a[0]), "r"(a[1]), "r"(a[2]), "r"(a[3]), "r"(b0), "r"(b1));
}

__device__ __forceinline__ float sigf(float x) { return 1.0f / (1.0f + __expf(-x)); }
__device__ __forceinline__ float tanhfast(float x) { return 2.0f / (1.0f + __expf(-2.0f * x)) - 1.0f; }

// shared fragment-address setup (same for all GEMM kernels)
struct Frag {
    uint32_t a_base[2], a_xc[2], b_base[4], b_xc[4];
};
__device__ __forceinline__ Frag make_frag(uint32_t sbase, int wid, int lane, uint32_t b_off) {
    Frag f;
    const int warp_m = wid & 3;
    const int warp_n = wid >> 2;
    const int koff = (lane >> 4) * 16;
#pragma unroll
    for (int tm = 0; tm < 2; tm++) {
        int row = warp_m * 32 + tm * 16 + (lane & 15);
        f.a_base[tm] = sbase + row * 128;
        f.a_xc[tm] = (uint32_t)(koff ^ ((row & 7) << 4));
    }
#pragma unroll
    for (int tn2 = 0; tn2 < 4; tn2++) {
        int row = warp_n * 64 + tn2 * 16 + (lane & 15);
        f.b_base[tn2] = sbase + b_off + row * 128;
        f.b_xc[tn2] = (uint32_t)(koff ^ ((row & 7) << 4));
    }
    return f;
}

// one chunk of compute: 4 ks-steps of ldsm+mma from stage offset
__device__ __forceinline__ void consume_chunk(const Frag& f, uint32_t stoff, float4 (&acc)[2][8]) {
#pragma unroll
    for (int ks = 0; ks < 4; ks++) {
        uint32_t a[2][4];
#pragma unroll
        for (int tm = 0; tm < 2; tm++)
            ldsm_x4(a[tm][0], a[tm][1], a[tm][2], a[tm][3],
                    f.a_base[tm] + stoff + ((uint32_t)(ks * 32) ^ f.a_xc[tm]));
        uint32_t b[4][4];
#pragma unroll
        for (int tn2 = 0; tn2 < 4; tn2++)
            ldsm_x4(b[tn2][0], b[tn2][1], b[tn2][2], b[tn2][3],
                    f.b_base[tn2] + stoff + ((uint32_t)(ks * 32) ^ f.b_xc[tn2]));
#pragma unroll
        for (int tm = 0; tm < 2; tm++)
#pragma unroll
            for (int tn2 = 0; tn2 < 4; tn2++) {
                mma_f16(acc[tm][tn2 * 2 + 0], a[tm], b[tn2][0], b[tn2][2]);
                mma_f16(acc[tm][tn2 * 2 + 1], a[tm], b[tn2][1], b[tn2][3]);
            }
    }
}

// fused LSTM epilogue shared by A(z=0) and finish kernels
__device__ __forceinline__ void lstm_epilogue(float4 (&acc)[2][8], int lane, int wid,
                                              int bm, int bn, const float* bias,
                                              float* c, half* hout, float* hq, int write_q) {
    const int warp_m = wid & 3;
    const int warp_n = wid >> 2;
    const bool even = !(lane & 1);
#pragma unroll
    for (int tm = 0; tm < 2; tm++) {
#pragma unroll
        for (int tn = 0; tn < 8; tn++) {
            float4 d = acc[tm][tn];
            float e0 = __shfl_xor_sync(0xffffffffu, d.x, 1);
            float e1 = __shfl_xor_sync(0xffffffffu, d.y, 1);
            float e2 = __shfl_xor_sync(0xffffffffu, d.z, 1);
            float e3 = __shfl_xor_sync(0xffffffffu, d.w, 1);
            if (even) {
                int col = bn + warp_n * 64 + tn * 8 + (lane & 3) * 2;
                int u = col >> 2;
                float4 bi = *(const float4*)&bias[col];
                int rA = bm + warp_m * 32 + tm * 16 + (lane >> 2);
#pragma unroll
                for (int rh = 0; rh < 2; rh++) {
                    int row = rA + rh * 8;
                    float gi = (rh ? d.z : d.x) + bi.x;
                    float gf = (rh ? d.w : d.y) + bi.y;
                    float gg = (rh ? e2 : e0) + bi.z;
                    float go = (rh ? e3 : e1) + bi.w;
                    size_t cidx = (size_t)row * DIM + u;
                    float cn = sigf(gf) * c[cidx] + sigf(gi) * tanhfast(gg);
                    c[cidx] = cn;
                    float hn = sigf(go) * tanhfast(cn);
                    hout[(size_t)row * 256 + u] = __float2half_rn(hn);
                    if (write_q) hq[(size_t)row * DIM + u] = hn;
                }
            }
        }
    }
}

// ---------------- prep / conv / init (unchanged from R11) ----------------------
struct PermArgs {
    const float* w_ih[3]; const float* w_hh[3];
    const float* b_ih[3]; const float* b_hh[3];
    int K1[3];
};
__global__ void prep_kernel(PermArgs pa) {
    int l = blockIdx.y;
    int K1 = pa.K1[l];
    half* wih = g_w_ih[l];
    half* whh = g_w_hh[l];
    int n_ih = NGATE * K1, n_hh = NGATE * DIM;
    int total = n_ih + n_hh + NGATE;
    for (int i = blockIdx.x * blockDim.x + threadIdx.x; i < total; i += gridDim.x * blockDim.x) {
        if (i < n_ih) {
            int r = i / K1, k = i - r * K1;
            int u = r >> 2, g = r & 3;
            wih[i] = __float2half_rn(pa.w_ih[l][(size_t)(g * 256 + u) * K1 + k]);
        } else if (i < n_ih + n_hh) {
            int j = i - n_ih;
            int r = j / DIM, k = j - r * DIM;
            int u = r >> 2, g = r & 3;
            whh[j] = __float2half_rn(pa.w_hh[l][(size_t)(g * 256 + u) * DIM + k]);
        } else {
            int r = i - n_ih - n_hh;
            int u = r >> 2, g = r & 3;
            g_bp[l * NGATE + r] = pa.b_ih[l][g * 256 + u] + pa.b_hh[l][g * 256 + u];
        }
    }
}

__global__ void feats_conv_kernel(const float* __restrict__ feats) {
    size_t i = ((size_t)blockIdx.x * blockDim.x + threadIdx.x) * 4;
    size_t stride = (size_t)gridDim.x * blockDim.x * 4;
    const size_t n = (size_t)N_NODES * DIM;
    for (; i < n; i += stride) {
        float4 v = *(const float4*)(feats + i);
        half2 h0 = __floats2half2_rn(v.x, v.y);
        half2 h1 = __floats2half2_rn(v.z, v.w);
        *(uint2*)(g_featsh + i) = make_uint2(*(uint32_t*)&h0, *(uint32_t*)&h1);
    }
}

__global__ void init_kernel(const int* __restrict__ seg) {
    size_t gid = (size_t)blockIdx.x * blockDim.x + threadIdx.x;
    size_t stride = (size_t)gridDim.x * blockDim.x;
    const size_t nq = (size_t)M_PAD * 512;
    const size_t nh = (size_t)2 * 3 * M_PAD * 256;
    const size_t nc = (size_t)3 * M_PAD * DIM;
    half z = __float2half_rn(0.0f);
    for (size_t i = gid; i < nq; i += stride) g_qstar[i] = z;
    for (size_t i = gid; i < nh; i += stride) g_hh[i] = z;
    for (size_t i = gid; i < nc; i += stride) g_c[i] = 0.0f;
    if (gid <= N_SEG) {
        int s = (int)gid;
        int lo = 0, hi = N_NODES;
        while (lo < hi) { int mid = (lo + hi) >> 1; if (seg[mid] < s) lo = mid + 1; else hi = mid; }
        g_start[s] = lo;
    }
}

// ---------------- pipeline constants --------------------------------------------
#define SM_BUF   16384
#define STAGE_SZ 32768
#define SMEM_GE  (3 * STAGE_SZ)

// ---------------- launch A: l0 full GEMM+LSTM  |  l1/l2 hh partials -------------
// grid (79, 8, 3). z=0: NC=12 full l0. z=1/2: NC=4 hh partial -> g_part.
__global__ __launch_bounds__(256, 2)
void gemmA(const half* __restrict__ qs, const half* __restrict__ wih0,
           const half* __restrict__ h0p, const half* __restrict__ whh0,
           const float* __restrict__ bias0, float* __restrict__ c0,
           half* __restrict__ h0out,
           const half* __restrict__ h1p, const half* __restrict__ whh1,
           const half* __restrict__ h2p, const half* __restrict__ whh2) {
    extern __shared__ __align__(128) char smem[];
    const uint32_t sbase = smem_u32(smem);
    const int tid = threadIdx.x;
    const int lane = tid & 31;
    const int wid = tid >> 5;
    const int bm = blockIdx.x * 128;
    const int bn = blockIdx.y * 128;
    const int z = blockIdx.z;

    const int r0 = tid >> 3;
    const int sg = tid & 7;
    const uint32_t so0 = (uint32_t)(r0 * 128 + ((sg * 16) ^ ((r0 & 7) << 4)));

    float4 acc[2][8];
#pragma unroll
    for (int i = 0; i < 2; i++)
#pragma unroll
        for (int j = 0; j < 8; j++) acc[i][j] = make_float4(0.f, 0.f, 0.f, 0.f);

    Frag frag = make_frag(sbase, wid, lane, SM_BUF);

    if (z == 0) {
        // ---- full l0 path: K1=512 ih + K=256 hh, NC=12 ----
        constexpr int C1 = 8, NC = 12;
        const half* a1p = qs + (size_t)(bm + r0) * 512 + sg * 8;
        const half* w1p = wih0 + (size_t)(bn + r0) * 512 + sg * 8;
        const half* a2p = h0p + (size_t)(bm + r0) * 256 + sg * 8;
        const half* w2p = whh0 + (size_t)(bn + r0) * 256 + sg * 8;

        auto load_chunk = [&](int g, int st) {
            const uint32_t sA = sbase + st * STAGE_SZ + so0;
            const uint32_t sB = sA + SM_BUF;
            if (g < C1) {
                const int off = g * 64;
#pragma unroll
                for (int q = 0; q < 4; q++) {
                    constexpr size_t ST = (size_t)32 * 512;
                    cp16(sA + q * 4096, a1p + q * ST + off);
                    cp16(sB + q * 4096, w1p + q * ST + off);
                }
            } else {
                const int off = (g - C1) * 64;
#pragma unroll
                for (int q = 0; q < 4; q++) {
                    constexpr size_t ST = (size_t)32 * 256;
                    cp16(sA + q * 4096, a2p + q * ST + off);
                    cp16(sB + q * 4096, w2p + q * ST + off);
                }
            }
            CP_COMMIT();
        };

        load_chunk(0, 0);
        load_chunk(1, 1);
        int st_cur = 0, st_nxt = 2;
#pragma unroll 1
        for (int g = 0; g < NC; g++) {
            if (g + 1 < NC) { CP_WAIT(1); } else { CP_WAIT(0); }
            __syncthreads();
            if (g + 2 < NC) load_chunk(g + 2, st_nxt);
            consume_chunk(frag, st_cur * STAGE_SZ, acc);
            st_cur = (st_cur == 2) ? 0 : st_cur + 1;
            st_nxt = (st_nxt == 2) ? 0 : st_nxt + 1;
        }
        lstm_epilogue(acc, lane, wid, bm, bn, bias0, c0, h0out, (float*)0, 0);
    } else {
        // ---- hh partial path: K=256, NC=4, store raw acc ----
        const half* A = (z == 1) ? h1p : h2p;
        const half* W = (z == 1) ? whh1 : whh2;
        const half* ap = A + (size_t)(bm + r0) * 256 + sg * 8;
        const half* wp = W + (size_t)(bn + r0) * 256 + sg * 8;

        auto load_chunk = [&](int g, int st) {
            const uint32_t sA = sbase + st * STAGE_SZ + so0;
            const uint32_t sB = sA + SM_BUF;
            const int off = g * 64;
#pragma unroll
            for (int q = 0; q < 4; q++) {
                constexpr size_t ST = (size_t)32 * 256;
                cp16(sA + q * 4096, ap + q * ST + off);
                cp16(sB + q * 4096, wp + q * ST + off);
            }
            CP_COMMIT();
        };

        load_chunk(0, 0);
        load_chunk(1, 1);
        int st_cur = 0, st_nxt = 2;
#pragma unroll 1
        for (int g = 0; g < 4; g++) {
            if (g + 1 < 4) { CP_WAIT(1); } else { CP_WAIT(0); }
            __syncthreads();
            if (g + 2 < 4) load_chunk(g + 2, st_nxt);
            consume_chunk(frag, st_cur * STAGE_SZ, acc);
            st_cur = (st_cur == 2) ? 0 : st_cur + 1;
            st_nxt = (st_nxt == 2) ? 0 : st_nxt + 1;
        }
        // store fragments: layout [cta][reg][tid] -> coalesced float4
        const size_t cta = (size_t)(z - 1) * NCTA + blockIdx.x * 8 + blockIdx.y;
        float4* pp = g_part + cta * (16 * 256) + tid;
#pragma unroll
        for (int i = 0; i < 2; i++)
#pragma unroll
            for (int j = 0; j < 8; j++) pp[(i * 8 + j) * 256] = acc[i][j];
    }
}

// ---------------- finish: ih GEMM (NC=4) + partial add + LSTM -------------------
__global__ __launch_bounds__(256, 2)
void gemmF(const half* __restrict__ A1, const half* __restrict__ W1,
           const float* __restrict__ bias, const float4* __restrict__ gpart,
           float* __restrict__ c, half* __restrict__ hout,
           float* __restrict__ hq, int write_q) {
    extern __shared__ __align__(128) char smem[];
    const uint32_t sbase = smem_u32(smem);
    const int tid = threadIdx.x;
    const int lane = tid & 31;
    const int wid = tid >> 5;
    const int bm = blockIdx.x * 128;
    const int bn = blockIdx.y * 128;

    const int r0 = tid >> 3;
    const int sg = tid & 7;
    const uint32_t so0 = (uint32_t)(r0 * 128 + ((sg * 16) ^ ((r0 & 7) << 4)));
    const half* ap = A1 + (size_t)(bm + r0) * 256 + sg * 8;
    const half* wp = W1 + (size_t)(bn + r0) * 256 + sg * 8;

    auto load_chunk = [&](int g, int st) {
        const uint32_t sA = sbase + st * STAGE_SZ + so0;
        const uint32_t sB = sA + SM_BUF;
        const int off = g * 64;
#pragma unroll
        for (int q = 0; q < 4; q++) {
            constexpr size_t ST = (size_t)32 * 256;
            cp16(sA + q * 4096, ap + q * ST + off);
            cp16(sB + q * 4096, wp + q * ST + off);
        }
        CP_COMMIT();
    };

    float4 acc[2][8];
#pragma unroll
    for (int i = 0; i < 2; i++)
#pragma unroll
        for (int j = 0; j < 8; j++) acc[i][j] = make_float4(0.f, 0.f, 0.f, 0.f);

    Frag frag = make_frag(sbase, wid, lane, SM_BUF);

    load_chunk(0, 0);
    load_chunk(1, 1);
    int st_cur = 0, st_nxt = 2;
#pragma unroll 1
    for (int g = 0; g < 4; g++) {
        if (g + 1 < 4) { CP_WAIT(1); } else { CP_WAIT(0); }
        __syncthreads();
        if (g + 2 < 4) load_chunk(g + 2, st_nxt);
        consume_chunk(frag, st_cur * STAGE_SZ, acc);
        st_cur = (st_cur == 2) ? 0 : st_cur + 1;
        st_nxt = (st_nxt == 2) ? 0 : st_nxt + 1;
    }

    // add hh partial (coalesced fragment layout)
    const size_t cta = (size_t)blockIdx.x * 8 + blockIdx.y;
    const float4* pp = gpart + cta * (16 * 256) + tid;
#pragma unroll
    for (int i = 0; i < 2; i++)
#pragma unroll
        for (int j = 0; j < 8; j++) {
            float4 p = pp[(i * 8 + j) * 256];
            acc[i][j].x += p.x; acc[i][j].y += p.y;
            acc[i][j].z += p.z; acc[i][j].w += p.w;
        }

    lstm_epilogue(acc, lane, wid, bm, bn, bias, c, hout, hq, write_q);
}

// ---------------- fused attention (unchanged from R11) --------------------------
__global__ void attn_kernel(const float* __restrict__ q, float* __restrict__ out) {
    const int s = blockIdx.x;
    const int lo = g_start[s], hi = g_start[s + 1];
    const int w = threadIdx.x >> 5;
    const int lane = threadIdx.x & 31;

    __shared__ float sm_m[8];
    __shared__ float sm_s[8];
    __shared__ float sm_r[8][256];

    float qf[8];
    *(float4*)&qf[0] = *(const float4*)(q + (size_t)s * DIM + lane * 8);
    *(float4*)&qf[4] = *(const float4*)(q + (size_t)s * DIM + lane * 8 + 4);

    float m = -INFINITY, ssum = 0.0f;
    float r[8];
#pragma unroll
    for (int j = 0; j < 8; j++) r[j] = 0.0f;

    for (int n = lo + w; n < hi; n += 8) {
        uint4 fv = *(const uint4*)(g_featsh + (size_t)n * DIM + lane * 8);
        float2 f0 = __half22float2(*(half2*)&fv.x);
        float2 f1 = __half22float2(*(half2*)&fv.y);
        float2 f2 = __half22float2(*(half2*)&fv.z);
        float2 f3 = __half22float2(*(half2*)&fv.w);
        float ff[8] = {f0.x, f0.y, f1.x, f1.y, f2.x, f2.y, f3.x, f3.y};
        float d = 0.0f;
#pragma unroll
        for (int j = 0; j < 8; j++) d = fmaf(ff[j], qf[j], d);
#pragma unroll
        for (int o = 16; o > 0; o >>= 1) d += __shfl_xor_sync(0xffffffffu, d, o);

        float mn = fmaxf(m, d);
        float sc = __expf(m - mn);
        float p  = __expf(d - mn);
        ssum = ssum * sc + p;
#pragma unroll
        for (int j = 0; j < 8; j++) r[j] = r[j] * sc + p * ff[j];
        m = mn;
    }

    if (lane == 0) { sm_m[w] = m; sm_s[w] = ssum; }
    *(float4*)&sm_r[w][lane * 8]     = *(float4*)&r[0];
    *(float4*)&sm_r[w][lane * 8 + 4] = *(float4*)&r[4];
    __syncthreads();

    const int t = threadIdx.x;
    float M = -INFINITY;
#pragma unroll
    for (int k = 0; k < 8; k++)
        if (sm_s[k] > 0.0f) M = fmaxf(M, sm_m[k]);
    float S = 0.0f, R = 0.0f;
#pragma unroll
    for (int k = 0; k < 8; k++) {
        if (sm_s[k] > 0.0f) {
            float sc = __expf(sm_m[k] - M);
            S += sm_s[k] * sc;
            R += sm_r[k][t] * sc;
        }
    }
    float rv = (S > 0.0f) ? R / S : 0.0f;
    float qv_ = q[(size_t)s * DIM + t];
    out[(size_t)s * QSTAR + t]       = qv_;
    out[(size_t)s * QSTAR + DIM + t] = rv;

    half* qs = g_qstar + (size_t)s * 512;
    qs[t]       = __float2half_rn(qv_);
    qs[256 + t] = __float2half_rn(rv);
}

// ---------------- host orchestration -------------------------------------------
extern "C" void kernel_launch(void* const* d_in, const int* in_sizes, int n_in,
                              void* d_out, int out_size) {
    const float* feats = (const float*)d_in[0];
    const int* seg = (const int*)d_in[1];
    float* out = (float*)d_out;

    PermArgs pa;
    for (int l = 0; l < 3; l++) {
        pa.w_ih[l] = (const float*)d_in[2 + 4 * l];
        pa.w_hh[l] = (const float*)d_in[3 + 4 * l];
        pa.b_ih[l] = (const float*)d_in[4 + 4 * l];
        pa.b_hh[l] = (const float*)d_in[5 + 4 * l];
        pa.K1[l] = (l == 0) ? QSTAR : DIM;
    }

    half *qs, *hh; float *c, *hq, *bp; half *wih[3], *whh[3]; float4* gpart;
    cudaGetSymbolAddress((void**)&qs, g_qstar);
    cudaGetSymbolAddress((void**)&hh, g_hh);
    cudaGetSymbolAddress((void**)&c, g_c);
    cudaGetSymbolAddress((void**)&hq, g_hq);
    cudaGetSymbolAddress((void**)&bp, g_bp);
    cudaGetSymbolAddress((void**)&gpart, g_part);
    {
        half* base_ih; half* base_hh;
        cudaGetSymbolAddress((void**)&base_ih, g_w_ih);
        cudaGetSymbolAddress((void**)&base_hh, g_w_hh);
        for (int l = 0; l < 3; l++) {
            wih[l] = base_ih + (size_t)l * NGATE * 512;
            whh[l] = base_hh + (size_t)l * NGATE * 256;
        }
    }

    cudaFuncSetAttribute(gemmA, cudaFuncAttributeMaxDynamicSharedMemorySize, SMEM_GE);
    cudaFuncSetAttribute(gemmF, cudaFuncAttributeMaxDynamicSharedMemorySize, SMEM_GE);

    dim3 pgrid(256, 3);
    prep_kernel<<<pgrid, 256>>>(pa);
    feats_conv_kernel<<<2048, 256>>>(feats);
    init_kernel<<<1184, 256>>>(seg);

    const size_t SDH = (size_t)M_PAD * 256;
    dim3 gA(M_PAD / 128, NGATE / 128, 3);
    dim3 gF(M_PAD / 128, NGATE / 128);

    for (int it = 0; it < NITER; it++) {
        half* hin  = hh + (size_t)(it & 1) * 3 * SDH;
        half* hout = hh + (size_t)((it + 1) & 1) * 3 * SDH;

        gemmA<<<gA, 256, SMEM_GE>>>(qs, wih[0], hin, whh[0], bp, c, hout,
                                    hin + 1 * SDH, whh[1],
                                    hin + 2 * SDH, whh[2]);
        gemmF<<<gF, 256, SMEM_GE>>>(hout, wih[1], bp + NGATE, gpart,
                                    c + 1 * (size_t)M_PAD * DIM, hout + 1 * SDH, hq, 0);
        gemmF<<<gF, 256, SMEM_GE>>>(hout + 1 * SDH, wih[2], bp + 2 * NGATE, gpart + PARTSZ,
                                    c + 2 * (size_t)M_PAD * DIM, hout + 2 * SDH, hq, 1);
        attn_kernel<<<N_SEG, 256>>>(hq, out);
    }
}